// round 1
// baseline (speedup 1.0000x reference)
#include <cuda_runtime.h>
#include <math.h>

// Problem constants
#define BN    8192        // B*H*W*T = 4*16*16*8
#define NCH   5           // 3 s2 + 2 s1 tokens per group
#define D_    768
#define A_    256
#define HEADS 8
#define HD    32
#define NJ    264         // A_ + HEADS (v-columns + per-head logit columns)
#define ROWS  (BN*NCH)    // 40960

// Scratch (static device globals; allocation-free)
__device__ float g_U[A_*HEADS];                 // folded query-key vectors, [a][h]
__device__ float g_bias[NJ];                    // [0..255] = bv_eff, [256..263] = logit const
__device__ float g_Wbig[D_*NJ];                 // folded weight, [d][j]
__device__ float g_XVL[(size_t)ROWS*NJ];        // per-token v (256) + logits (8)
__device__ float g_pool[(size_t)BN*A_];         // attention-pooled vectors
__device__ float g_hasenc[BN];                  // 1.0 if any valid key else 0.0

// ---------------------------------------------------------------------------
// K0a: tiny folds. U[a,h] = sum_d Wk[h*32+d, a] * q[h*32+d] * scale
//      bias[j<256] = bv[j] + Wv[j,:]·b_in
//      bias[256+h] = U[:,h]·b_in + (q_h*scale)·bk_hblk
// ---------------------------------------------------------------------------
__global__ void k_prep(const float* __restrict__ Wk, const float* __restrict__ bk,
                       const float* __restrict__ Wv, const float* __restrict__ bv,
                       const float* __restrict__ bin, const float* __restrict__ q)
{
    int a = threadIdx.x;  // 0..255
    const float scale = rsqrtf((float)HD);

    #pragma unroll
    for (int h = 0; h < HEADS; h++) {
        float u = 0.f;
        #pragma unroll 8
        for (int d = 0; d < HD; d++) {
            int row = h*HD + d;
            u += Wk[row*A_ + a] * (q[row] * scale);
        }
        g_U[a*HEADS + h] = u;
    }

    float bb = bv[a];
    for (int i = 0; i < A_; i++) bb += Wv[a*A_ + i] * bin[i];
    g_bias[a] = bb;

    __syncthreads();

    if (a < HEADS) {
        float c = 0.f;
        for (int i = 0; i < A_; i++) c += g_U[i*HEADS + a] * bin[i];
        for (int d = 0; d < HD; d++) {
            int row = a*HD + d;
            c += q[row] * scale * bk[row];
        }
        g_bias[A_ + a] = c;
    }
}

// ---------------------------------------------------------------------------
// K0b: Wbig[d][j] = sum_a Win[a,d] * Cat[a,j]
//      Cat[a, j<256] = Wv[j, a];  Cat[a, 256+h] = U[a, h]
// 16x16 tiled GEMM, 768 x 264, K = 256.
// ---------------------------------------------------------------------------
__global__ void k_wbig(const float* __restrict__ Win, const float* __restrict__ Wv)
{
    __shared__ float sA[16][17];  // [a_local][d_local]
    __shared__ float sC[16][17];  // [j_local][a_local]
    int tx = threadIdx.x, ty = threadIdx.y;
    int d = blockIdx.y*16 + ty;
    int j = blockIdx.x*16 + tx;
    float acc = 0.f;

    for (int a0 = 0; a0 < A_; a0 += 16) {
        sA[ty][tx] = Win[(size_t)(a0+ty)*D_ + blockIdx.y*16 + tx];
        int jg = blockIdx.x*16 + ty;
        int aa = a0 + tx;
        float cv = 0.f;
        if (jg < A_)       cv = Wv[(size_t)jg*A_ + aa];
        else if (jg < NJ)  cv = g_U[aa*HEADS + (jg - A_)];
        sC[ty][tx] = cv;
        __syncthreads();
        #pragma unroll
        for (int al = 0; al < 16; al++) acc += sA[al][ty] * sC[tx][al];
        __syncthreads();
    }
    if (j < NJ) g_Wbig[(size_t)d*NJ + j] = acc;
}

// ---------------------------------------------------------------------------
// K1: main gather-GEMM. XVL[r][j] = tokens[r] · Wbig[:,j] + bias[j]
// M = 40960 (rows gathered from s2/s1), N = 264, K = 768.
// 64x64 tiles, 256 threads, 4x4 register micro-tile, K-step 16.
// ---------------------------------------------------------------------------
__global__ __launch_bounds__(256) void k_gemm1(const float* __restrict__ s2,
                                               const float* __restrict__ s1)
{
    __shared__ float sA[16][68];  // [k][m]
    __shared__ float sB[16][68];  // [k][j]
    int tid = threadIdx.x;
    int r0 = blockIdx.y * 64;
    int j0 = blockIdx.x * 64;

    // A-tile loader: each thread owns one row, one 4-float chunk of k
    int mrow = tid >> 2;              // 0..63
    int kc   = (tid & 3) * 4;         // 0,4,8,12
    {
        // fallthrough: pointer computed below
    }
    int r = r0 + mrow;
    int g = r / 5, s = r - g*5;
    const float* rowp = (s < 3) ? (s2 + (size_t)(g*3 + s) * D_)
                                : (s1 + (size_t)(g*2 + (s-3)) * D_);

    // B-tile loader indices
    int jl = tid & 63;
    int kb = tid >> 6;                // 0..3

    // compute indices
    int tx = tid & 15, ty = tid >> 4;
    float acc[4][4] = {};

    for (int k0 = 0; k0 < D_; k0 += 16) {
        float4 av = *(const float4*)(rowp + k0 + kc);
        sA[kc+0][mrow] = av.x;
        sA[kc+1][mrow] = av.y;
        sA[kc+2][mrow] = av.z;
        sA[kc+3][mrow] = av.w;

        #pragma unroll
        for (int i = 0; i < 4; i++) {
            int kk = kb + i*4;
            int jg = j0 + jl;
            sB[kk][jl] = (jg < NJ) ? g_Wbig[(size_t)(k0+kk)*NJ + jg] : 0.f;
        }
        __syncthreads();

        #pragma unroll
        for (int k = 0; k < 16; k++) {
            float4 a4 = *(const float4*)&sA[k][ty*4];
            float4 b4 = *(const float4*)&sB[k][tx*4];
            float aw[4] = {a4.x, a4.y, a4.z, a4.w};
            float bw[4] = {b4.x, b4.y, b4.z, b4.w};
            #pragma unroll
            for (int i = 0; i < 4; i++)
                #pragma unroll
                for (int jj = 0; jj < 4; jj++)
                    acc[i][jj] += aw[i] * bw[jj];
        }
        __syncthreads();
    }

    int jbase = j0 + tx*4;
    if (jbase < NJ) {
        float4 bo;
        bo.x = g_bias[jbase+0]; bo.y = g_bias[jbase+1];
        bo.z = g_bias[jbase+2]; bo.w = g_bias[jbase+3];
        #pragma unroll
        for (int i = 0; i < 4; i++) {
            int rr = r0 + ty*4 + i;
            float4 o;
            o.x = acc[i][0] + bo.x;
            o.y = acc[i][1] + bo.y;
            o.z = acc[i][2] + bo.z;
            o.w = acc[i][3] + bo.w;
            *(float4*)&g_XVL[(size_t)rr*NJ + jbase] = o;
        }
    }
}

// ---------------------------------------------------------------------------
// K2: per-group masked softmax over N=5 + attention pooling.
// One block per group; thread j owns pooled dim j (head = j/32).
// ---------------------------------------------------------------------------
__global__ void k_attn(const int* __restrict__ m2, const int* __restrict__ m1,
                       float* __restrict__ maskOut)
{
    int g = blockIdx.x;
    int j = threadIdx.x;  // 0..255
    int h = j >> 5;

    int mv[5];
    #pragma unroll
    for (int n = 0; n < 5; n++)
        mv[n] = (n < 3) ? m2[g*3 + n] : m1[g*2 + (n-3)];

    const float* base = &g_XVL[(size_t)g * 5 * NJ];

    float l[5]; bool valid[5]; bool any = false;
    float mx = -1e30f;
    #pragma unroll
    for (int n = 0; n < 5; n++) {
        valid[n] = (mv[n] == 1);
        l[n] = base[(size_t)n*NJ + A_ + h];
        if (valid[n]) { any = true; mx = fmaxf(mx, l[n]); }
    }
    float w[5]; float ssum = 0.f;
    #pragma unroll
    for (int n = 0; n < 5; n++) {
        w[n] = valid[n] ? expf(l[n] - mx) : 0.f;
        ssum += w[n];
    }
    float inv = any ? (1.f / ssum) : 0.f;

    float pool = 0.f;
    #pragma unroll
    for (int n = 0; n < 5; n++)
        pool += (w[n] * inv) * base[(size_t)n*NJ + j];

    g_pool[(size_t)g*A_ + j] = pool;

    if (j == 0) {
        float hv = any ? 1.f : 0.f;
        g_hasenc[g] = hv;
        if (maskOut) maskOut[g] = hv;   // agg_mask (as float 0/1), tail of d_out
    }
}

// ---------------------------------------------------------------------------
// K3: out = pool @ Woutᵀ + b_out, then zero rows without any valid key.
// M = 8192, N = 768, K = 256. Same tiling as K1.
// ---------------------------------------------------------------------------
__global__ __launch_bounds__(256) void k_gemm2(const float* __restrict__ Wout,
                                               const float* __restrict__ bout,
                                               float* __restrict__ out)
{
    __shared__ float sA[16][68];  // [k][m]
    __shared__ float sB[16][68];  // [k][j]
    int tid = threadIdx.x;
    int m0 = blockIdx.y * 64;
    int j0 = blockIdx.x * 64;

    int mrow = tid >> 2;
    int kc   = (tid & 3) * 4;
    int klB  = tid & 15;
    int jbB  = tid >> 4;

    int tx = tid & 15, ty = tid >> 4;
    float acc[4][4] = {};

    for (int k0 = 0; k0 < A_; k0 += 16) {
        float4 av = *(const float4*)(g_pool + (size_t)(m0 + mrow)*A_ + k0 + kc);
        sA[kc+0][mrow] = av.x;
        sA[kc+1][mrow] = av.y;
        sA[kc+2][mrow] = av.z;
        sA[kc+3][mrow] = av.w;

        #pragma unroll
        for (int i = 0; i < 4; i++) {
            int jj = jbB + 16*i;
            sB[klB][jj] = Wout[(size_t)(j0 + jj)*A_ + k0 + klB];
        }
        __syncthreads();

        #pragma unroll
        for (int k = 0; k < 16; k++) {
            float4 a4 = *(const float4*)&sA[k][ty*4];
            float4 b4 = *(const float4*)&sB[k][tx*4];
            float aw[4] = {a4.x, a4.y, a4.z, a4.w};
            float bw[4] = {b4.x, b4.y, b4.z, b4.w};
            #pragma unroll
            for (int i = 0; i < 4; i++)
                #pragma unroll
                for (int jj = 0; jj < 4; jj++)
                    acc[i][jj] += aw[i] * bw[jj];
        }
        __syncthreads();
    }

    int jbase = j0 + tx*4;
    float4 bo = *(const float4*)(bout + jbase);
    #pragma unroll
    for (int i = 0; i < 4; i++) {
        int m = m0 + ty*4 + i;
        float he = g_hasenc[m];      // 1.0 or 0.0
        float4 o;
        o.x = he * (acc[i][0] + bo.x);
        o.y = he * (acc[i][1] + bo.y);
        o.z = he * (acc[i][2] + bo.z);
        o.w = he * (acc[i][3] + bo.w);
        *(float4*)&out[(size_t)m*D_ + jbase] = o;
    }
}

// ---------------------------------------------------------------------------
extern "C" void kernel_launch(void* const* d_in, const int* in_sizes, int n_in,
                              void* d_out, int out_size)
{
    const float* s2   = (const float*)d_in[0];   // (BN,3,768)
    const float* s1   = (const float*)d_in[1];   // (BN,2,768)
    const float* Win  = (const float*)d_in[2];   // (256,768)
    const float* bin  = (const float*)d_in[3];   // (256)
    const float* Wk   = (const float*)d_in[4];   // (256,256)
    const float* bk   = (const float*)d_in[5];   // (256)
    const float* Wv   = (const float*)d_in[6];   // (256,256)
    const float* bv   = (const float*)d_in[7];   // (256)
    const float* Wout = (const float*)d_in[8];   // (768,256)
    const float* bout = (const float*)d_in[9];   // (768)
    const float* q    = (const float*)d_in[10];  // (1,1,256)
    const int*   m2   = (const int*)d_in[11];    // (BN,3)
    const int*   m1   = (const int*)d_in[12];    // (BN,2)

    float* out = (float*)d_out;
    // Tuple output: out (BN*D) first; agg_mask (BN) appended if the buffer has room.
    float* maskOut = (out_size >= (int)((size_t)BN*D_ + BN)) ? (out + (size_t)BN*D_)
                                                             : nullptr;

    k_prep<<<1, 256>>>(Wk, bk, Wv, bv, bin, q);
    k_wbig<<<dim3((NJ+15)/16, D_/16), dim3(16,16)>>>(Win, Wv);
    k_gemm1<<<dim3((NJ+63)/64, ROWS/64), 256>>>(s2, s1);
    k_attn<<<BN, 256>>>(m2, m1, maskOut);
    k_gemm2<<<dim3(D_/64, BN/64), 256>>>(Wout, bout, out);
}

// round 2
// speedup vs baseline: 1.1404x; 1.1404x over previous
#include <cuda_runtime.h>
#include <math.h>

// Problem constants
#define BN    8192        // B*H*W*T = 4*16*16*8
#define D_    768
#define A_    256
#define HEADS 8
#define HD    32

// Scratch (static device globals; allocation-free)
__device__ float g_U[A_*HEADS];                  // r[a][h] = scale * Wk[hblk,:]^T q_h
__device__ float g_bias[A_+HEADS];               // [0..255] bias_v; [256..263] logit const c_h
__device__ float g_u[HEADS*D_];                  // u[h][d] = Win^T r_h
__device__ float g_Wbigv[(size_t)A_*D_];         // Wv @ Win, [c][d]
__device__ float g_p[(size_t)BN*HEADS*D_];       // per-head pooled tokens [g][h][d]
__device__ float g_pool[(size_t)BN*A_];          // pooled v vectors
__device__ float g_hasenc[BN];                   // 1.0 if any valid key else 0.0

// ---------------------------------------------------------------------------
// K_prep: r[a][h], bias_v[c], logit consts c_h.
// ---------------------------------------------------------------------------
__global__ void k_prep(const float* __restrict__ Wk, const float* __restrict__ bk,
                       const float* __restrict__ Wv, const float* __restrict__ bv,
                       const float* __restrict__ bin, const float* __restrict__ q)
{
    int a = threadIdx.x;  // 0..255
    const float scale = rsqrtf((float)HD);

    #pragma unroll
    for (int h = 0; h < HEADS; h++) {
        float u = 0.f;
        #pragma unroll 8
        for (int d = 0; d < HD; d++) {
            int row = h*HD + d;
            u += Wk[row*A_ + a] * (q[row] * scale);
        }
        g_U[a*HEADS + h] = u;
    }

    float bb = bv[a];
    for (int i = 0; i < A_; i++) bb += Wv[a*A_ + i] * bin[i];
    g_bias[a] = bb;

    __syncthreads();

    if (a < HEADS) {
        float c = 0.f;
        for (int i = 0; i < A_; i++) c += g_U[i*HEADS + a] * bin[i];
        for (int d = 0; d < HD; d++) {
            int row = a*HD + d;
            c += q[row] * scale * bk[row];
        }
        g_bias[A_ + a] = c;
    }
}

// ---------------------------------------------------------------------------
// K_u: u[h][d] = sum_a r[a][h] * Win[a][d].   grid = 3 blocks x 256 thr.
// ---------------------------------------------------------------------------
__global__ void k_u(const float* __restrict__ Win)
{
    __shared__ float rs[A_*HEADS];
    int tid = threadIdx.x;
    for (int i = tid; i < A_*HEADS; i += 256) rs[i] = g_U[i];
    __syncthreads();

    int d = blockIdx.x*256 + tid;   // 0..767
    float acc[HEADS] = {};
    for (int a = 0; a < A_; a++) {
        float w = Win[(size_t)a*D_ + d];
        #pragma unroll
        for (int h = 0; h < HEADS; h++) acc[h] += w * rs[a*HEADS + h];
    }
    #pragma unroll
    for (int h = 0; h < HEADS; h++) g_u[h*D_ + d] = acc[h];
}

// ---------------------------------------------------------------------------
// K_wbigv: W_bigv[c][d] = sum_a Wv[c][a] * Win[a][d].  (256x768, K=256)
// ---------------------------------------------------------------------------
__global__ void k_wbigv(const float* __restrict__ Win, const float* __restrict__ Wv)
{
    __shared__ float sA[16][17];  // [c][a]
    __shared__ float sB[16][17];  // [a][d]
    int tx = threadIdx.x, ty = threadIdx.y;
    int c = blockIdx.y*16 + ty;
    int d = blockIdx.x*16 + tx;
    float acc = 0.f;

    for (int a0 = 0; a0 < A_; a0 += 16) {
        sA[ty][tx] = Wv[(size_t)c*A_ + a0 + tx];
        sB[ty][tx] = Win[(size_t)(a0+ty)*D_ + d];
        __syncthreads();
        #pragma unroll
        for (int al = 0; al < 16; al++) acc += sA[ty][al] * sB[al][tx];
        __syncthreads();
    }
    g_Wbigv[(size_t)c*D_ + d] = acc;
}

// ---------------------------------------------------------------------------
// K_fused: per 2 groups: load 10 token rows to smem, compute logits vs u,
// masked softmax, then weighted pooling -> g_p.  grid = BN/2 blocks.
// ---------------------------------------------------------------------------
__global__ __launch_bounds__(256) void k_fused(const float* __restrict__ s2,
                                               const float* __restrict__ s1,
                                               const int* __restrict__ m2,
                                               const int* __restrict__ m1,
                                               float* __restrict__ maskOut)
{
    __shared__ float Ts[10][772];     // 772 = 768 + 4 pad (bank rotate, 16B aligned rows)
    __shared__ float ls[10][8];       // logits [row][h]
    __shared__ float ws[2][8][5];     // normalized weights

    int tid = threadIdx.x;
    int gb0 = blockIdx.x * 2;

    // Phase 1: load tokens (float4, coalesced)
    for (int idx = tid; idx < 10*192; idx += 256) {
        int row = idx / 192, c4 = idx % 192;
        int g = row / 5, s = row - g*5;
        int gg = gb0 + g;
        const float* src = (s < 3) ? s2 + (size_t)(gg*3 + s) * D_
                                   : s1 + (size_t)(gg*2 + (s-3)) * D_;
        float4 v = *(const float4*)(src + c4*4);
        *(float4*)&Ts[row][c4*4] = v;
    }
    __syncthreads();

    // Phase 2: logits. 160 threads: (row 0..9, h 0..7) x 2 halves of d.
    if (tid < 160) {
        int pair = tid >> 1, half = tid & 1;
        int row = pair >> 3, h = pair & 7;
        const float4* up = (const float4*)(g_u + (size_t)h*D_) + half*96;
        const float4* tp = (const float4*)&Ts[row][0] + half*96;
        float s = 0.f;
        #pragma unroll 8
        for (int i = 0; i < 96; i++) {
            float4 a = tp[i]; float4 b = up[i];
            s += a.x*b.x + a.y*b.y + a.z*b.z + a.w*b.w;
        }
        s += __shfl_xor_sync(0xFFFFFFFF, s, 1);
        if (half == 0) ls[row][h] = s + g_bias[A_ + h];
    }
    __syncthreads();

    // Phase 3: masked softmax per (g, h)
    if (tid < 16) {
        int g = tid >> 3, h = tid & 7;
        int gg = gb0 + g;
        int mv[5];
        #pragma unroll
        for (int n = 0; n < 5; n++)
            mv[n] = (n < 3) ? m2[gg*3 + n] : m1[gg*2 + (n-3)];
        float l[5]; bool valid[5]; bool any = false; float mx = -1e30f;
        #pragma unroll
        for (int n = 0; n < 5; n++) {
            valid[n] = (mv[n] == 1);
            l[n] = ls[g*5 + n][h];
            if (valid[n]) { any = true; mx = fmaxf(mx, l[n]); }
        }
        float w[5], ssum = 0.f;
        #pragma unroll
        for (int n = 0; n < 5; n++) {
            w[n] = valid[n] ? expf(l[n] - mx) : 0.f;
            ssum += w[n];
        }
        float inv = any ? (1.f/ssum) : 0.f;
        #pragma unroll
        for (int n = 0; n < 5; n++) ws[g][h][n] = w[n]*inv;
        if (h == 0) {
            float he = any ? 1.f : 0.f;
            g_hasenc[gg] = he;
            if (maskOut) maskOut[gg] = he;
        }
    }
    __syncthreads();

    // Phase 4: pooling -> g_p[gg][h][d]
    for (int idx = tid; idx < 3072; idx += 256) {   // 2*8*192 float4 outputs
        int d4 = idx % 192;
        int h  = (idx / 192) & 7;
        int g  = idx / 1536;
        float w0 = ws[g][h][0], w1 = ws[g][h][1], w2 = ws[g][h][2],
              w3 = ws[g][h][3], w4 = ws[g][h][4];
        const int rb = g*5;
        float4 t0 = *(const float4*)&Ts[rb+0][d4*4];
        float4 t1 = *(const float4*)&Ts[rb+1][d4*4];
        float4 t2 = *(const float4*)&Ts[rb+2][d4*4];
        float4 t3 = *(const float4*)&Ts[rb+3][d4*4];
        float4 t4 = *(const float4*)&Ts[rb+4][d4*4];
        float4 o;
        o.x = w0*t0.x + w1*t1.x + w2*t2.x + w3*t3.x + w4*t4.x;
        o.y = w0*t0.y + w1*t1.y + w2*t2.y + w3*t3.y + w4*t4.y;
        o.z = w0*t0.z + w1*t1.z + w2*t2.z + w3*t3.z + w4*t4.z;
        o.w = w0*t0.w + w1*t1.w + w2*t2.w + w3*t3.w + w4*t4.w;
        *(float4*)&g_p[((size_t)(gb0+g)*HEADS + h)*D_ + d4*4] = o;
    }
}

// ---------------------------------------------------------------------------
// K_vpool: pooled_v[g][h*32+j] = W_bigv[h*32+j,:] . p[g][h,:] + bias_v
// Per block: 128 g-rows x 32 cols (one head), K=768.  grid = (64, 8).
// ---------------------------------------------------------------------------
__global__ __launch_bounds__(256) void k_vpool()
{
    __shared__ float sA[128][36];  // [g_local][k]  (36: 16B-aligned rows, bank rotate)
    __shared__ float sB[32][36];   // [k][j]
    int tid = threadIdx.x;
    int h  = blockIdx.y;
    int g0 = blockIdx.x * 128;

    int tx = tid & 7, ty = tid >> 3;          // compute: 8 x 32 thread grid
    int arow = tid >> 1, akc = (tid & 1)*16;  // A loader
    int bj = tid & 31, bk = (tid >> 5)*4;     // B loader

    const float* Ap = g_p + ((size_t)(g0 + arow)*HEADS + h)*D_ + akc;
    const float* Bp = g_Wbigv + (size_t)(h*32 + bj)*D_ + bk;

    float acc[4][4] = {};

    for (int k0 = 0; k0 < D_; k0 += 32) {
        #pragma unroll
        for (int i = 0; i < 4; i++) {
            float4 v = *(const float4*)(Ap + k0 + i*4);
            *(float4*)&sA[arow][akc + i*4] = v;
        }
        {
            float4 v = *(const float4*)(Bp + k0);
            sB[bk+0][bj] = v.x; sB[bk+1][bj] = v.y;
            sB[bk+2][bj] = v.z; sB[bk+3][bj] = v.w;
        }
        __syncthreads();

        #pragma unroll
        for (int k = 0; k < 32; k++) {
            float4 b4 = *(const float4*)&sB[k][tx*4];
            float a0 = sA[ty*4+0][k], a1 = sA[ty*4+1][k],
                  a2 = sA[ty*4+2][k], a3 = sA[ty*4+3][k];
            acc[0][0] += a0*b4.x; acc[0][1] += a0*b4.y; acc[0][2] += a0*b4.z; acc[0][3] += a0*b4.w;
            acc[1][0] += a1*b4.x; acc[1][1] += a1*b4.y; acc[1][2] += a1*b4.z; acc[1][3] += a1*b4.w;
            acc[2][0] += a2*b4.x; acc[2][1] += a2*b4.y; acc[2][2] += a2*b4.z; acc[2][3] += a2*b4.w;
            acc[3][0] += a3*b4.x; acc[3][1] += a3*b4.y; acc[3][2] += a3*b4.z; acc[3][3] += a3*b4.w;
        }
        __syncthreads();
    }

    int c = h*32 + tx*4;
    float4 bo = *(const float4*)&g_bias[c];
    #pragma unroll
    for (int i = 0; i < 4; i++) {
        int g = g0 + ty*4 + i;
        float4 o;
        o.x = acc[i][0] + bo.x; o.y = acc[i][1] + bo.y;
        o.z = acc[i][2] + bo.z; o.w = acc[i][3] + bo.w;
        *(float4*)&g_pool[(size_t)g*A_ + c] = o;
    }
}

// ---------------------------------------------------------------------------
// K_out: out = pooled_v @ Wout^T + bout, zeroed where no valid key.
// M=8192, N=768, K=256.  64x64 tiles.
// ---------------------------------------------------------------------------
__global__ __launch_bounds__(256) void k_out(const float* __restrict__ Wout,
                                             const float* __restrict__ bout,
                                             float* __restrict__ out)
{
    __shared__ float sA[16][68];  // [k][m]
    __shared__ float sB[16][68];  // [k][j]
    int tid = threadIdx.x;
    int m0 = blockIdx.y * 64;
    int j0 = blockIdx.x * 64;

    int mrow = tid >> 2;
    int kc   = (tid & 3) * 4;
    int klB  = tid & 15;
    int jbB  = tid >> 4;

    int tx = tid & 15, ty = tid >> 4;
    float acc[4][4] = {};

    for (int k0 = 0; k0 < A_; k0 += 16) {
        float4 av = *(const float4*)(g_pool + (size_t)(m0 + mrow)*A_ + k0 + kc);
        sA[kc+0][mrow] = av.x;
        sA[kc+1][mrow] = av.y;
        sA[kc+2][mrow] = av.z;
        sA[kc+3][mrow] = av.w;

        #pragma unroll
        for (int i = 0; i < 4; i++) {
            int jj = jbB + 16*i;
            sB[klB][jj] = Wout[(size_t)(j0 + jj)*A_ + k0 + klB];
        }
        __syncthreads();

        #pragma unroll
        for (int k = 0; k < 16; k++) {
            float4 a4 = *(const float4*)&sA[k][ty*4];
            float4 b4 = *(const float4*)&sB[k][tx*4];
            float aw[4] = {a4.x, a4.y, a4.z, a4.w};
            float bw[4] = {b4.x, b4.y, b4.z, b4.w};
            #pragma unroll
            for (int i = 0; i < 4; i++)
                #pragma unroll
                for (int jj = 0; jj < 4; jj++)
                    acc[i][jj] += aw[i] * bw[jj];
        }
        __syncthreads();
    }

    int jbase = j0 + tx*4;
    float4 bo = *(const float4*)(bout + jbase);
    #pragma unroll
    for (int i = 0; i < 4; i++) {
        int m = m0 + ty*4 + i;
        float he = g_hasenc[m];
        float4 o;
        o.x = he * (acc[i][0] + bo.x);
        o.y = he * (acc[i][1] + bo.y);
        o.z = he * (acc[i][2] + bo.z);
        o.w = he * (acc[i][3] + bo.w);
        *(float4*)&out[(size_t)m*D_ + jbase] = o;
    }
}

// ---------------------------------------------------------------------------
extern "C" void kernel_launch(void* const* d_in, const int* in_sizes, int n_in,
                              void* d_out, int out_size)
{
    const float* s2   = (const float*)d_in[0];   // (BN,3,768)
    const float* s1   = (const float*)d_in[1];   // (BN,2,768)
    const float* Win  = (const float*)d_in[2];   // (256,768)
    const float* bin  = (const float*)d_in[3];   // (256)
    const float* Wk   = (const float*)d_in[4];   // (256,256)
    const float* bk   = (const float*)d_in[5];   // (256)
    const float* Wv   = (const float*)d_in[6];   // (256,256)
    const float* bv   = (const float*)d_in[7];   // (256)
    const float* Wout = (const float*)d_in[8];   // (768,256)
    const float* bout = (const float*)d_in[9];   // (768)
    const float* q    = (const float*)d_in[10];  // (1,1,256)
    const int*   m2   = (const int*)d_in[11];    // (BN,3)
    const int*   m1   = (const int*)d_in[12];    // (BN,2)

    float* out = (float*)d_out;
    float* maskOut = (out_size >= (int)((size_t)BN*D_ + BN)) ? (out + (size_t)BN*D_)
                                                             : nullptr;

    k_prep<<<1, 256>>>(Wk, bk, Wv, bv, bin, q);
    k_u<<<3, 256>>>(Win);
    k_wbigv<<<dim3(48, 16), dim3(16, 16)>>>(Win, Wv);
    k_fused<<<BN/2, 256>>>(s2, s1, m2, m1, maskOut);
    k_vpool<<<dim3(64, 8), 256>>>();
    k_out<<<dim3(12, 128), 256>>>(Wout, bout, out);
}

// round 3
// speedup vs baseline: 1.2048x; 1.0564x over previous
#include <cuda_runtime.h>
#include <math.h>

// Problem constants
#define BN    8192        // B*H*W*T = 4*16*16*8
#define D_    768
#define A_    256
#define HEADS 8
#define HD    32

// Scratch (static device globals; allocation-free)
__device__ float g_U[A_*HEADS];                  // r[a][h] = scale * Wk[hblk,:]^T q_h
__device__ float g_bias[A_+HEADS];               // [0..255] bias_v; [256..263] logit const c_h
__device__ float g_uT[D_*HEADS];                 // u transposed: [d][h]
__device__ float g_Wbigv[(size_t)A_*D_];         // Wv @ Win, [c][d]
__device__ float g_p[(size_t)HEADS*BN*D_];       // pooled tokens, [h][g][d]  (head-major!)
__device__ float g_pool[(size_t)BN*A_];          // pooled v vectors [g][c]
__device__ float g_hasenc[BN];                   // 1.0 if any valid key else 0.0

// ---------------------------------------------------------------------------
// K_prep: r[a][h], bias_v[c], logit consts c_h.
// ---------------------------------------------------------------------------
__global__ void k_prep(const float* __restrict__ Wk, const float* __restrict__ bk,
                       const float* __restrict__ Wv, const float* __restrict__ bv,
                       const float* __restrict__ bin, const float* __restrict__ q)
{
    int a = threadIdx.x;  // 0..255
    const float scale = rsqrtf((float)HD);

    #pragma unroll
    for (int h = 0; h < HEADS; h++) {
        float u = 0.f;
        #pragma unroll 8
        for (int d = 0; d < HD; d++) {
            int row = h*HD + d;
            u += Wk[row*A_ + a] * (q[row] * scale);
        }
        g_U[a*HEADS + h] = u;
    }

    float bb = bv[a];
    for (int i = 0; i < A_; i++) bb += Wv[a*A_ + i] * bin[i];
    g_bias[a] = bb;

    __syncthreads();

    if (a < HEADS) {
        float c = 0.f;
        for (int i = 0; i < A_; i++) c += g_U[i*HEADS + a] * bin[i];
        for (int d = 0; d < HD; d++) {
            int row = a*HD + d;
            c += q[row] * scale * bk[row];
        }
        g_bias[A_ + a] = c;
    }
}

// ---------------------------------------------------------------------------
// K_u: uT[d][h] = sum_a r[a][h] * Win[a][d].   grid = 3 blocks x 256 thr.
// ---------------------------------------------------------------------------
__global__ void k_u(const float* __restrict__ Win)
{
    __shared__ float rs[A_*HEADS];
    int tid = threadIdx.x;
    for (int i = tid; i < A_*HEADS; i += 256) rs[i] = g_U[i];
    __syncthreads();

    int d = blockIdx.x*256 + tid;   // 0..767
    float acc[HEADS] = {};
    for (int a = 0; a < A_; a++) {
        float w = Win[(size_t)a*D_ + d];
        #pragma unroll
        for (int h = 0; h < HEADS; h++) acc[h] += w * rs[a*HEADS + h];
    }
    #pragma unroll
    for (int h = 0; h < HEADS; h++) g_uT[d*HEADS + h] = acc[h];
}

// ---------------------------------------------------------------------------
// K_wbigv: W_bigv[c][d] = sum_a Wv[c][a] * Win[a][d].  (256x768, K=256)
// ---------------------------------------------------------------------------
__global__ void k_wbigv(const float* __restrict__ Win, const float* __restrict__ Wv)
{
    __shared__ float sA[16][17];  // [c][a]
    __shared__ float sB[16][17];  // [a][d]
    int tx = threadIdx.x, ty = threadIdx.y;
    int c = blockIdx.y*16 + ty;
    int d = blockIdx.x*16 + tx;
    float acc = 0.f;

    for (int a0 = 0; a0 < A_; a0 += 16) {
        sA[ty][tx] = Wv[(size_t)c*A_ + a0 + tx];
        sB[ty][tx] = Win[(size_t)(a0+ty)*D_ + d];
        __syncthreads();
        #pragma unroll
        for (int al = 0; al < 16; al++) acc += sA[ty][al] * sB[al][tx];
        __syncthreads();
    }
    g_Wbigv[(size_t)c*D_ + d] = acc;
}

// ---------------------------------------------------------------------------
// K_fused: per 2 groups: tokens -> logits -> masked softmax -> pooled tokens.
// grid = BN/2, 256 threads.
// ---------------------------------------------------------------------------
__global__ __launch_bounds__(256) void k_fused(const float* __restrict__ s2,
                                               const float* __restrict__ s1,
                                               const int* __restrict__ m2,
                                               const int* __restrict__ m1,
                                               float* __restrict__ maskOut)
{
    __shared__ float Ts[10][772];     // token rows (4-float pad)
    __shared__ float ls[10][8];       // logits [row][h]
    __shared__ float ws[2][8][5];     // normalized weights

    int tid = threadIdx.x;
    int gb0 = blockIdx.x * 2;
    int wid = tid >> 5, lane = tid & 31;

    // Phase 1: load tokens (float4, coalesced)
    for (int idx = tid; idx < 10*192; idx += 256) {
        int row = idx / 192, c4 = idx % 192;
        int g = row / 5, s = row - g*5;
        int gg = gb0 + g;
        const float* src = (s < 3) ? s2 + (size_t)(gg*3 + s) * D_
                                   : s1 + (size_t)(gg*2 + (s-3)) * D_;
        *(float4*)&Ts[row][c4*4] = *(const float4*)(src + c4*4);
    }
    __syncthreads();

    // Phase 2: logits, warp-per-row, 8 independent accumulators per lane.
    for (int row = wid; row < 10; row += 8) {
        float acc[8] = {};
        #pragma unroll
        for (int i = 0; i < 24; i++) {
            int d = lane + 32*i;
            float t = Ts[row][d];
            float4 u0 = *(const float4*)(g_uT + d*8);
            float4 u1 = *(const float4*)(g_uT + d*8 + 4);
            acc[0] += t*u0.x; acc[1] += t*u0.y; acc[2] += t*u0.z; acc[3] += t*u0.w;
            acc[4] += t*u1.x; acc[5] += t*u1.y; acc[6] += t*u1.z; acc[7] += t*u1.w;
        }
        #pragma unroll
        for (int off = 16; off; off >>= 1) {
            #pragma unroll
            for (int h = 0; h < 8; h++)
                acc[h] += __shfl_xor_sync(0xFFFFFFFF, acc[h], off);
        }
        if (lane < 8) ls[row][lane] = acc[lane] + g_bias[A_ + lane];
    }
    __syncthreads();

    // Phase 3: masked softmax per (g, h)
    if (tid < 16) {
        int g = tid >> 3, h = tid & 7;
        int gg = gb0 + g;
        int mv[5];
        #pragma unroll
        for (int n = 0; n < 5; n++)
            mv[n] = (n < 3) ? m2[gg*3 + n] : m1[gg*2 + (n-3)];
        float l[5]; bool valid[5]; bool any = false; float mx = -1e30f;
        #pragma unroll
        for (int n = 0; n < 5; n++) {
            valid[n] = (mv[n] == 1);
            l[n] = ls[g*5 + n][h];
            if (valid[n]) { any = true; mx = fmaxf(mx, l[n]); }
        }
        float w[5], ssum = 0.f;
        #pragma unroll
        for (int n = 0; n < 5; n++) {
            w[n] = valid[n] ? expf(l[n] - mx) : 0.f;
            ssum += w[n];
        }
        float inv = any ? (1.f/ssum) : 0.f;
        #pragma unroll
        for (int n = 0; n < 5; n++) ws[g][h][n] = w[n]*inv;
        if (h == 0) {
            float he = any ? 1.f : 0.f;
            g_hasenc[gg] = he;
            if (maskOut) maskOut[gg] = he;
        }
    }
    __syncthreads();

    // Phase 4: pooling. Each thread: one (g,d4), reads 5 token float4 ONCE,
    // emits all 8 head outputs.  g_p layout: [h][g][d].
    for (int idx = tid; idx < 384; idx += 256) {
        int d4 = idx % 192, g = idx / 192;
        int gg = gb0 + g;
        const int rb = g*5;
        float4 t0 = *(const float4*)&Ts[rb+0][d4*4];
        float4 t1 = *(const float4*)&Ts[rb+1][d4*4];
        float4 t2 = *(const float4*)&Ts[rb+2][d4*4];
        float4 t3 = *(const float4*)&Ts[rb+3][d4*4];
        float4 t4 = *(const float4*)&Ts[rb+4][d4*4];
        #pragma unroll
        for (int h = 0; h < 8; h++) {
            float w0 = ws[g][h][0], w1 = ws[g][h][1], w2 = ws[g][h][2],
                  w3 = ws[g][h][3], w4 = ws[g][h][4];
            float4 o;
            o.x = w0*t0.x + w1*t1.x + w2*t2.x + w3*t3.x + w4*t4.x;
            o.y = w0*t0.y + w1*t1.y + w2*t2.y + w3*t3.y + w4*t4.y;
            o.z = w0*t0.z + w1*t1.z + w2*t2.z + w3*t3.z + w4*t4.z;
            o.w = w0*t0.w + w1*t1.w + w2*t2.w + w3*t3.w + w4*t4.w;
            *(float4*)&g_p[((size_t)h*BN + gg)*D_ + d4*4] = o;
        }
    }
}

// ---------------------------------------------------------------------------
// K_vpool: pooled_v[g][h*32+j] = W_bigv[h*32+j,:] . p[h][g,:] + bias_v
// Tile: 128 g x 32 j (one head), K=768, 128 threads, 8x4 micro-tile.
// grid = (BN/128, HEADS).
// ---------------------------------------------------------------------------
__global__ __launch_bounds__(128) void k_vpool()
{
    __shared__ float sA[16][132];  // [k][g]  (transposed)
    __shared__ float sB[16][36];   // [k][j]
    int tid = threadIdx.x;
    int h  = blockIdx.y;
    int g0 = blockIdx.x * 128;

    int tm = tid >> 3;             // 0..15 -> 8 g-rows each
    int tn = tid & 7;              // 0..7  -> 4 j-cols each

    const float* Ap = g_p + ((size_t)h*BN + g0 + tid)*D_;
    const float* Bp = g_Wbigv + (size_t)(h*32 + (tid & 31))*D_ + ((tid >> 5) * 4);

    float acc[8][4] = {};

    for (int k0 = 0; k0 < D_; k0 += 16) {
        #pragma unroll
        for (int c = 0; c < 4; c++) {
            float4 v = *(const float4*)(Ap + k0 + c*4);
            sA[c*4+0][tid] = v.x; sA[c*4+1][tid] = v.y;
            sA[c*4+2][tid] = v.z; sA[c*4+3][tid] = v.w;
        }
        {
            int j = tid & 31, kr = (tid >> 5) * 4;
            float4 v = *(const float4*)(Bp + k0);
            sB[kr+0][j] = v.x; sB[kr+1][j] = v.y;
            sB[kr+2][j] = v.z; sB[kr+3][j] = v.w;
        }
        __syncthreads();

        #pragma unroll
        for (int k = 0; k < 16; k++) {
            float4 a0 = *(const float4*)&sA[k][tm*8];
            float4 a1 = *(const float4*)&sA[k][tm*8+4];
            float4 b  = *(const float4*)&sB[k][tn*4];
            float av[8] = {a0.x,a0.y,a0.z,a0.w,a1.x,a1.y,a1.z,a1.w};
            #pragma unroll
            for (int i = 0; i < 8; i++) {
                acc[i][0] += av[i]*b.x; acc[i][1] += av[i]*b.y;
                acc[i][2] += av[i]*b.z; acc[i][3] += av[i]*b.w;
            }
        }
        __syncthreads();
    }

    int c = h*32 + tn*4;
    float4 bo = *(const float4*)&g_bias[c];
    #pragma unroll
    for (int i = 0; i < 8; i++) {
        int g = g0 + tm*8 + i;
        float4 o;
        o.x = acc[i][0] + bo.x; o.y = acc[i][1] + bo.y;
        o.z = acc[i][2] + bo.z; o.w = acc[i][3] + bo.w;
        *(float4*)&g_pool[(size_t)g*A_ + c] = o;
    }
}

// ---------------------------------------------------------------------------
// K_out: out = pooled_v @ Wout^T + bout, zeroed where no valid key.
// Tile: 64 m x 128 j, K=256, 128 threads, 8x8 micro-tile. grid = (6, 128).
// ---------------------------------------------------------------------------
__global__ __launch_bounds__(128) void k_out(const float* __restrict__ Wout,
                                             const float* __restrict__ bout,
                                             float* __restrict__ out)
{
    __shared__ float sA[16][68];   // [k][m]
    __shared__ float sB[16][132];  // [k][j]
    int tid = threadIdx.x;
    int m0 = blockIdx.y * 64;
    int j0 = blockIdx.x * 128;

    int tm = tid >> 4;             // 0..7  -> 8 m-rows each
    int tn = tid & 15;             // 0..15 -> 8 j-cols each

    const float* Ap = g_pool + (size_t)(m0 + (tid >> 1))*A_ + (tid & 1)*8;
    const float* Bp = Wout + (size_t)(j0 + tid)*A_;

    float acc[8][8] = {};

    for (int k0 = 0; k0 < A_; k0 += 16) {
        {
            int row = tid >> 1, kc = (tid & 1)*8;
            float4 v0 = *(const float4*)(Ap + k0);
            float4 v1 = *(const float4*)(Ap + k0 + 4);
            sA[kc+0][row] = v0.x; sA[kc+1][row] = v0.y;
            sA[kc+2][row] = v0.z; sA[kc+3][row] = v0.w;
            sA[kc+4][row] = v1.x; sA[kc+5][row] = v1.y;
            sA[kc+6][row] = v1.z; sA[kc+7][row] = v1.w;
        }
        #pragma unroll
        for (int c = 0; c < 4; c++) {
            float4 v = *(const float4*)(Bp + k0 + c*4);
            sB[c*4+0][tid] = v.x; sB[c*4+1][tid] = v.y;
            sB[c*4+2][tid] = v.z; sB[c*4+3][tid] = v.w;
        }
        __syncthreads();

        #pragma unroll
        for (int k = 0; k < 16; k++) {
            float4 a0 = *(const float4*)&sA[k][tm*8];
            float4 a1 = *(const float4*)&sA[k][tm*8+4];
            float4 b0 = *(const float4*)&sB[k][tn*8];
            float4 b1 = *(const float4*)&sB[k][tn*8+4];
            float av[8] = {a0.x,a0.y,a0.z,a0.w,a1.x,a1.y,a1.z,a1.w};
            float bv[8] = {b0.x,b0.y,b0.z,b0.w,b1.x,b1.y,b1.z,b1.w};
            #pragma unroll
            for (int i = 0; i < 8; i++)
                #pragma unroll
                for (int jj = 0; jj < 8; jj++)
                    acc[i][jj] += av[i]*bv[jj];
        }
        __syncthreads();
    }

    int jb = j0 + tn*8;
    float4 bo0 = *(const float4*)(bout + jb);
    float4 bo1 = *(const float4*)(bout + jb + 4);
    float bb[8] = {bo0.x,bo0.y,bo0.z,bo0.w,bo1.x,bo1.y,bo1.z,bo1.w};
    #pragma unroll
    for (int i = 0; i < 8; i++) {
        int m = m0 + tm*8 + i;
        float he = g_hasenc[m];
        float4 o0, o1;
        o0.x = he*(acc[i][0]+bb[0]); o0.y = he*(acc[i][1]+bb[1]);
        o0.z = he*(acc[i][2]+bb[2]); o0.w = he*(acc[i][3]+bb[3]);
        o1.x = he*(acc[i][4]+bb[4]); o1.y = he*(acc[i][5]+bb[5]);
        o1.z = he*(acc[i][6]+bb[6]); o1.w = he*(acc[i][7]+bb[7]);
        *(float4*)&out[(size_t)m*D_ + jb]     = o0;
        *(float4*)&out[(size_t)m*D_ + jb + 4] = o1;
    }
}

// ---------------------------------------------------------------------------
extern "C" void kernel_launch(void* const* d_in, const int* in_sizes, int n_in,
                              void* d_out, int out_size)
{
    const float* s2   = (const float*)d_in[0];   // (BN,3,768)
    const float* s1   = (const float*)d_in[1];   // (BN,2,768)
    const float* Win  = (const float*)d_in[2];   // (256,768)
    const float* bin  = (const float*)d_in[3];   // (256)
    const float* Wk   = (const float*)d_in[4];   // (256,256)
    const float* bk   = (const float*)d_in[5];   // (256)
    const float* Wv   = (const float*)d_in[6];   // (256,256)
    const float* bv   = (const float*)d_in[7];   // (256)
    const float* Wout = (const float*)d_in[8];   // (768,256)
    const float* bout = (const float*)d_in[9];   // (768)
    const float* q    = (const float*)d_in[10];  // (1,1,256)
    const int*   m2   = (const int*)d_in[11];    // (BN,3)
    const int*   m1   = (const int*)d_in[12];    // (BN,2)

    float* out = (float*)d_out;
    float* maskOut = (out_size >= (int)((size_t)BN*D_ + BN)) ? (out + (size_t)BN*D_)
                                                             : nullptr;

    k_prep<<<1, 256>>>(Wk, bk, Wv, bv, bin, q);
    k_u<<<3, 256>>>(Win);
    k_wbigv<<<dim3(48, 16), dim3(16, 16)>>>(Win, Wv);
    k_fused<<<BN/2, 256>>>(s2, s1, m2, m1, maskOut);
    k_vpool<<<dim3(BN/128, HEADS), 128>>>();
    k_out<<<dim3(6, 128), 128>>>(Wout, bout, out);
}

// round 4
// speedup vs baseline: 1.2438x; 1.0324x over previous
#include <cuda_runtime.h>
#include <math.h>

// Problem constants
#define BN    8192        // B*H*W*T
#define D_    768
#define A_    256
#define HEADS 8
#define HD    32

// Scratch (static device globals; allocation-free)
__device__ float g_U[A_*HEADS];                  // r[a][h]
__device__ float g_bias[A_+HEADS];               // [0..255] bias_v; [256..263] logit const
__device__ float g_uT[D_*HEADS];                 // u transposed: [d][h]
__device__ float g_Wbigv[(size_t)A_*D_];         // Wv @ Win, [c][d]
__device__ float g_w[(size_t)BN*HEADS*5];        // softmax weights [g][h][n]
__device__ float g_pool[(size_t)BN*A_];          // pooled v vectors [g][c]
__device__ float g_hasenc[BN];                   // 1.0 if any valid key else 0.0

// ---------------------------------------------------------------------------
// K_prep: r[a][h], bias_v[c], logit consts c_h.
// ---------------------------------------------------------------------------
__global__ void k_prep(const float* __restrict__ Wk, const float* __restrict__ bk,
                       const float* __restrict__ Wv, const float* __restrict__ bv,
                       const float* __restrict__ bin, const float* __restrict__ q)
{
    int a = threadIdx.x;  // 0..255
    const float scale = rsqrtf((float)HD);

    #pragma unroll
    for (int h = 0; h < HEADS; h++) {
        float u = 0.f;
        #pragma unroll 8
        for (int d = 0; d < HD; d++) {
            int row = h*HD + d;
            u += Wk[row*A_ + a] * (q[row] * scale);
        }
        g_U[a*HEADS + h] = u;
    }

    float bb = bv[a];
    for (int i = 0; i < A_; i++) bb += Wv[a*A_ + i] * bin[i];
    g_bias[a] = bb;

    __syncthreads();

    if (a < HEADS) {
        float c = 0.f;
        for (int i = 0; i < A_; i++) c += g_U[i*HEADS + a] * bin[i];
        for (int d = 0; d < HD; d++) {
            int row = a*HD + d;
            c += q[row] * scale * bk[row];
        }
        g_bias[A_ + a] = c;
    }
}

// ---------------------------------------------------------------------------
// K_u: uT[d][h] = sum_a r[a][h] * Win[a][d].
// ---------------------------------------------------------------------------
__global__ void k_u(const float* __restrict__ Win)
{
    __shared__ float rs[A_*HEADS];
    int tid = threadIdx.x;
    for (int i = tid; i < A_*HEADS; i += 256) rs[i] = g_U[i];
    __syncthreads();

    int d = blockIdx.x*256 + tid;
    float acc[HEADS] = {};
    for (int a = 0; a < A_; a++) {
        float w = Win[(size_t)a*D_ + d];
        #pragma unroll
        for (int h = 0; h < HEADS; h++) acc[h] += w * rs[a*HEADS + h];
    }
    #pragma unroll
    for (int h = 0; h < HEADS; h++) g_uT[d*HEADS + h] = acc[h];
}

// ---------------------------------------------------------------------------
// K_wbigv: W_bigv[c][d] = sum_a Wv[c][a] * Win[a][d].  (256x768, K=256)
// ---------------------------------------------------------------------------
__global__ void k_wbigv(const float* __restrict__ Win, const float* __restrict__ Wv)
{
    __shared__ float sA[16][17];
    __shared__ float sB[16][17];
    int tx = threadIdx.x, ty = threadIdx.y;
    int c = blockIdx.y*16 + ty;
    int d = blockIdx.x*16 + tx;
    float acc = 0.f;

    for (int a0 = 0; a0 < A_; a0 += 16) {
        sA[ty][tx] = Wv[(size_t)c*A_ + a0 + tx];
        sB[ty][tx] = Win[(size_t)(a0+ty)*D_ + d];
        __syncthreads();
        #pragma unroll
        for (int al = 0; al < 16; al++) acc += sA[ty][al] * sB[al][tx];
        __syncthreads();
    }
    g_Wbigv[(size_t)c*D_ + d] = acc;
}

// ---------------------------------------------------------------------------
// K_logits: warp-per-group. Stream tokens from GMEM, 8 head accumulators per
// lane, butterfly reduce, in-warp masked softmax, write weights.
// grid = BN/8 blocks x 256 threads.
// ---------------------------------------------------------------------------
__global__ __launch_bounds__(256) void k_logits(const float* __restrict__ s2,
                                                const float* __restrict__ s1,
                                                const int* __restrict__ m2,
                                                const int* __restrict__ m1,
                                                float* __restrict__ maskOut)
{
    __shared__ float sL[8][5][8];   // [warp][row][head]

    int tid = threadIdx.x;
    int wid = tid >> 5, lane = tid & 31;
    int g = blockIdx.x * 8 + wid;

    for (int n = 0; n < 5; n++) {
        const float* src = (n < 3) ? s2 + (size_t)(g*3 + n) * D_
                                   : s1 + (size_t)(g*2 + (n-3)) * D_;
        float acc[8] = {};
        #pragma unroll 6
        for (int i = 0; i < 24; i++) {
            int d = lane + 32*i;
            float t = __ldg(src + d);
            float4 u0 = *(const float4*)(g_uT + d*8);
            float4 u1 = *(const float4*)(g_uT + d*8 + 4);
            acc[0] += t*u0.x; acc[1] += t*u0.y; acc[2] += t*u0.z; acc[3] += t*u0.w;
            acc[4] += t*u1.x; acc[5] += t*u1.y; acc[6] += t*u1.z; acc[7] += t*u1.w;
        }
        #pragma unroll
        for (int off = 16; off; off >>= 1)
            #pragma unroll
            for (int h = 0; h < 8; h++)
                acc[h] += __shfl_xor_sync(0xFFFFFFFF, acc[h], off);
        if (lane == 0) {
            #pragma unroll
            for (int h = 0; h < 8; h++) sL[wid][n][h] = acc[h];
        }
    }
    __syncwarp();

    if (lane < 8) {
        int h = lane;
        int mv[5];
        #pragma unroll
        for (int n = 0; n < 5; n++)
            mv[n] = (n < 3) ? m2[g*3 + n] : m1[g*2 + (n-3)];
        float l[5]; bool valid[5]; bool any = false; float mx = -1e30f;
        #pragma unroll
        for (int n = 0; n < 5; n++) {
            valid[n] = (mv[n] == 1);
            l[n] = sL[wid][n][h] + g_bias[A_ + h];
            if (valid[n]) { any = true; mx = fmaxf(mx, l[n]); }
        }
        float w[5], ssum = 0.f;
        #pragma unroll
        for (int n = 0; n < 5; n++) {
            w[n] = valid[n] ? expf(l[n] - mx) : 0.f;
            ssum += w[n];
        }
        float inv = any ? (1.f/ssum) : 0.f;
        float* wp = g_w + (size_t)g*40 + h*5;
        #pragma unroll
        for (int n = 0; n < 5; n++) wp[n] = w[n]*inv;
        if (h == 0) {
            float he = any ? 1.f : 0.f;
            g_hasenc[g] = he;
            if (maskOut) maskOut[g] = he;
        }
    }
}

// ---------------------------------------------------------------------------
// K_vpool_f: fused pooling + v-projection.
// Block: 32 groups x 256 cols, K=768 in chunks of 16.
// Per chunk: load raw token tiles + Wbigv tile; build 8 per-head pooled
// A-tiles in smem (weights in regs); 4x8 micro-tile FFMA GEMM.
// grid = BN/32, 256 threads.
// ---------------------------------------------------------------------------
#define VG 32
#define KC 16
__global__ __launch_bounds__(256) void k_vpool_f(const float* __restrict__ s2,
                                                 const float* __restrict__ s1)
{
    __shared__ float sT[VG*5*17];        // [g*5+n][k], row stride 17 (conflict-free pooling)
    __shared__ float sPool[8*580];       // h plane stride 580 = 16*36+4; [k*36+g]
    __shared__ float sB[KC*260];         // [k][c], row stride 260

    int tid = threadIdx.x;
    int g0 = blockIdx.x * VG;

    // pooling-build role: fixed (hb, gb)
    int hb = tid >> 5, gb = tid & 31;
    float w0, w1, w2, w3, w4;
    {
        const float* wp = g_w + (size_t)(g0 + gb)*40 + hb*5;
        w0 = wp[0]; w1 = wp[1]; w2 = wp[2]; w3 = wp[3]; w4 = wp[4];
    }

    // GEMM role: tm = warp (4 g-rows), tn = lane (8 cols, single head)
    int tm = tid >> 5;       // 0..7
    int tn = tid & 31;       // 0..31
    int h2 = tn >> 2;        // head of my 8 cols

    float acc[4][8] = {};

    for (int k0 = 0; k0 < D_; k0 += KC) {
        // load token tiles: 160 rows x 4 float4
        for (int idx = tid; idx < VG*5*4; idx += 256) {
            int row = idx >> 2, part = idx & 3;
            int g = row / 5, n = row - g*5;
            int gg = g0 + g;
            const float* src = (n < 3) ? s2 + (size_t)(gg*3 + n) * D_
                                       : s1 + (size_t)(gg*2 + (n-3)) * D_;
            float4 v = *(const float4*)(src + k0 + part*4);
            float* dst = &sT[row*17 + part*4];
            dst[0] = v.x; dst[1] = v.y; dst[2] = v.z; dst[3] = v.w;
        }
        // load B tile: 256 c x 4 float4 -> transposed [k][c]
        for (int idx = tid; idx < 1024; idx += 256) {
            int c = idx >> 2, part = idx & 3;
            float4 v = *(const float4*)(g_Wbigv + (size_t)c*D_ + k0 + part*4);
            sB[(part*4+0)*260 + c] = v.x;
            sB[(part*4+1)*260 + c] = v.y;
            sB[(part*4+2)*260 + c] = v.z;
            sB[(part*4+3)*260 + c] = v.w;
        }
        __syncthreads();

        // build pooled A: sPool[hb][k][gb]
        {
            const float* t0 = &sT[(gb*5+0)*17];
            const float* t1 = &sT[(gb*5+1)*17];
            const float* t2 = &sT[(gb*5+2)*17];
            const float* t3 = &sT[(gb*5+3)*17];
            const float* t4 = &sT[(gb*5+4)*17];
            float* pp = &sPool[hb*580 + gb];
            #pragma unroll
            for (int k = 0; k < KC; k++)
                pp[k*36] = w0*t0[k] + w1*t1[k] + w2*t2[k] + w3*t3[k] + w4*t4[k];
        }
        __syncthreads();

        // GEMM
        #pragma unroll
        for (int k = 0; k < KC; k++) {
            float4 a = *(const float4*)&sPool[h2*580 + k*36 + tm*4];
            float4 b0 = *(const float4*)&sB[k*260 + tn*8];
            float4 b1 = *(const float4*)&sB[k*260 + tn*8 + 4];
            float av[4] = {a.x, a.y, a.z, a.w};
            float bv[8] = {b0.x,b0.y,b0.z,b0.w,b1.x,b1.y,b1.z,b1.w};
            #pragma unroll
            for (int i = 0; i < 4; i++)
                #pragma unroll
                for (int j = 0; j < 8; j++)
                    acc[i][j] += av[i]*bv[j];
        }
        __syncthreads();
    }

    int c = tn*8;
    float4 bo0 = *(const float4*)&g_bias[c];
    float4 bo1 = *(const float4*)&g_bias[c+4];
    float bb[8] = {bo0.x,bo0.y,bo0.z,bo0.w,bo1.x,bo1.y,bo1.z,bo1.w};
    #pragma unroll
    for (int i = 0; i < 4; i++) {
        int g = g0 + tm*4 + i;
        float4 o0, o1;
        o0.x = acc[i][0]+bb[0]; o0.y = acc[i][1]+bb[1];
        o0.z = acc[i][2]+bb[2]; o0.w = acc[i][3]+bb[3];
        o1.x = acc[i][4]+bb[4]; o1.y = acc[i][5]+bb[5];
        o1.z = acc[i][6]+bb[6]; o1.w = acc[i][7]+bb[7];
        *(float4*)&g_pool[(size_t)g*A_ + c]     = o0;
        *(float4*)&g_pool[(size_t)g*A_ + c + 4] = o1;
    }
}

// ---------------------------------------------------------------------------
// K_out: out = pooled_v @ Wout^T + bout, zeroed where no valid key.
// Tile: 64 m x 128 j, K=256, 128 threads, 8x8 micro-tile. grid = (6, 128).
// ---------------------------------------------------------------------------
__global__ __launch_bounds__(128) void k_out(const float* __restrict__ Wout,
                                             const float* __restrict__ bout,
                                             float* __restrict__ out)
{
    __shared__ float sA[16][68];   // [k][m]
    __shared__ float sB[16][132];  // [k][j]
    int tid = threadIdx.x;
    int m0 = blockIdx.y * 64;
    int j0 = blockIdx.x * 128;

    int tm = tid >> 4;
    int tn = tid & 15;

    const float* Ap = g_pool + (size_t)(m0 + (tid >> 1))*A_ + (tid & 1)*8;
    const float* Bp = Wout + (size_t)(j0 + tid)*A_;

    float acc[8][8] = {};

    for (int k0 = 0; k0 < A_; k0 += 16) {
        {
            int row = tid >> 1, kc = (tid & 1)*8;
            float4 v0 = *(const float4*)(Ap + k0);
            float4 v1 = *(const float4*)(Ap + k0 + 4);
            sA[kc+0][row] = v0.x; sA[kc+1][row] = v0.y;
            sA[kc+2][row] = v0.z; sA[kc+3][row] = v0.w;
            sA[kc+4][row] = v1.x; sA[kc+5][row] = v1.y;
            sA[kc+6][row] = v1.z; sA[kc+7][row] = v1.w;
        }
        #pragma unroll
        for (int c = 0; c < 4; c++) {
            float4 v = *(const float4*)(Bp + k0 + c*4);
            sB[c*4+0][tid] = v.x; sB[c*4+1][tid] = v.y;
            sB[c*4+2][tid] = v.z; sB[c*4+3][tid] = v.w;
        }
        __syncthreads();

        #pragma unroll
        for (int k = 0; k < 16; k++) {
            float4 a0 = *(const float4*)&sA[k][tm*8];
            float4 a1 = *(const float4*)&sA[k][tm*8+4];
            float4 b0 = *(const float4*)&sB[k][tn*8];
            float4 b1 = *(const float4*)&sB[k][tn*8+4];
            float av[8] = {a0.x,a0.y,a0.z,a0.w,a1.x,a1.y,a1.z,a1.w};
            float bv[8] = {b0.x,b0.y,b0.z,b0.w,b1.x,b1.y,b1.z,b1.w};
            #pragma unroll
            for (int i = 0; i < 8; i++)
                #pragma unroll
                for (int jj = 0; jj < 8; jj++)
                    acc[i][jj] += av[i]*bv[jj];
        }
        __syncthreads();
    }

    int jb = j0 + tn*8;
    float4 bo0 = *(const float4*)(bout + jb);
    float4 bo1 = *(const float4*)(bout + jb + 4);
    float bb[8] = {bo0.x,bo0.y,bo0.z,bo0.w,bo1.x,bo1.y,bo1.z,bo1.w};
    #pragma unroll
    for (int i = 0; i < 8; i++) {
        int m = m0 + tm*8 + i;
        float he = g_hasenc[m];
        float4 o0, o1;
        o0.x = he*(acc[i][0]+bb[0]); o0.y = he*(acc[i][1]+bb[1]);
        o0.z = he*(acc[i][2]+bb[2]); o0.w = he*(acc[i][3]+bb[3]);
        o1.x = he*(acc[i][4]+bb[4]); o1.y = he*(acc[i][5]+bb[5]);
        o1.z = he*(acc[i][6]+bb[6]); o1.w = he*(acc[i][7]+bb[7]);
        *(float4*)&out[(size_t)m*D_ + jb]     = o0;
        *(float4*)&out[(size_t)m*D_ + jb + 4] = o1;
    }
}

// ---------------------------------------------------------------------------
extern "C" void kernel_launch(void* const* d_in, const int* in_sizes, int n_in,
                              void* d_out, int out_size)
{
    const float* s2   = (const float*)d_in[0];
    const float* s1   = (const float*)d_in[1];
    const float* Win  = (const float*)d_in[2];
    const float* bin  = (const float*)d_in[3];
    const float* Wk   = (const float*)d_in[4];
    const float* bk   = (const float*)d_in[5];
    const float* Wv   = (const float*)d_in[6];
    const float* bv   = (const float*)d_in[7];
    const float* Wout = (const float*)d_in[8];
    const float* bout = (const float*)d_in[9];
    const float* q    = (const float*)d_in[10];
    const int*   m2   = (const int*)d_in[11];
    const int*   m1   = (const int*)d_in[12];

    float* out = (float*)d_out;
    float* maskOut = (out_size >= (int)((size_t)BN*D_ + BN)) ? (out + (size_t)BN*D_)
                                                             : nullptr;

    k_prep<<<1, 256>>>(Wk, bk, Wv, bv, bin, q);
    k_u<<<3, 256>>>(Win);
    k_wbigv<<<dim3(48, 16), dim3(16, 16)>>>(Win, Wv);
    k_logits<<<BN/8, 256>>>(s2, s1, m2, m1, maskOut);
    k_vpool_f<<<BN/VG, 256>>>(s2, s1);
    k_out<<<dim3(6, 128), 128>>>(Wout, bout, out);
}

// round 5
// speedup vs baseline: 1.2475x; 1.0029x over previous
#include <cuda_runtime.h>
#include <math.h>

// Problem constants
#define BN    8192        // B*H*W*T
#define D_    768
#define A_    256
#define HEADS 8
#define HD    32

// Scratch (static device globals; allocation-free)
__device__ float g_U[A_*HEADS];                  // r[a][h]
__device__ float g_bias[A_+HEADS];               // [0..255] bias_v; [256..263] logit const
__device__ float g_uT[D_*HEADS];                 // u transposed: [d][h]
__device__ float g_Wbigv[(size_t)A_*D_];         // Wv @ Win, [c][d]
__device__ float g_w[(size_t)BN*HEADS*5];        // softmax weights [g][h][n]
__device__ float g_pool[(size_t)BN*A_];          // pooled v vectors [g][c]
__device__ float g_hasenc[BN];                   // 1.0 if any valid key else 0.0

// ---------------------------------------------------------------------------
// K_prep: r[a][h], bias_v[c], logit consts c_h.
// ---------------------------------------------------------------------------
__global__ void k_prep(const float* __restrict__ Wk, const float* __restrict__ bk,
                       const float* __restrict__ Wv, const float* __restrict__ bv,
                       const float* __restrict__ bin, const float* __restrict__ q)
{
    int a = threadIdx.x;  // 0..255
    const float scale = rsqrtf((float)HD);

    #pragma unroll
    for (int h = 0; h < HEADS; h++) {
        float u = 0.f;
        #pragma unroll 8
        for (int d = 0; d < HD; d++) {
            int row = h*HD + d;
            u += Wk[row*A_ + a] * (q[row] * scale);
        }
        g_U[a*HEADS + h] = u;
    }

    float bb = bv[a];
    for (int i = 0; i < A_; i++) bb += Wv[a*A_ + i] * bin[i];
    g_bias[a] = bb;

    __syncthreads();

    if (a < HEADS) {
        float c = 0.f;
        for (int i = 0; i < A_; i++) c += g_U[i*HEADS + a] * bin[i];
        for (int d = 0; d < HD; d++) {
            int row = a*HD + d;
            c += q[row] * scale * bk[row];
        }
        g_bias[A_ + a] = c;
    }
}

// ---------------------------------------------------------------------------
// K_u: uT[d][h] = sum_a r[a][h] * Win[a][d].
// ---------------------------------------------------------------------------
__global__ void k_u(const float* __restrict__ Win)
{
    __shared__ float rs[A_*HEADS];
    int tid = threadIdx.x;
    for (int i = tid; i < A_*HEADS; i += 256) rs[i] = g_U[i];
    __syncthreads();

    int d = blockIdx.x*256 + tid;
    float acc[HEADS] = {};
    for (int a = 0; a < A_; a++) {
        float w = Win[(size_t)a*D_ + d];
        #pragma unroll
        for (int h = 0; h < HEADS; h++) acc[h] += w * rs[a*HEADS + h];
    }
    #pragma unroll
    for (int h = 0; h < HEADS; h++) g_uT[d*HEADS + h] = acc[h];
}

// ---------------------------------------------------------------------------
// K_wbigv: W_bigv[c][d] = sum_a Wv[c][a] * Win[a][d].  (256x768, K=256)
// ---------------------------------------------------------------------------
__global__ void k_wbigv(const float* __restrict__ Win, const float* __restrict__ Wv)
{
    __shared__ float sA[16][17];
    __shared__ float sB[16][17];
    int tx = threadIdx.x, ty = threadIdx.y;
    int c = blockIdx.y*16 + ty;
    int d = blockIdx.x*16 + tx;
    float acc = 0.f;

    for (int a0 = 0; a0 < A_; a0 += 16) {
        sA[ty][tx] = Wv[(size_t)c*A_ + a0 + tx];
        sB[ty][tx] = Win[(size_t)(a0+ty)*D_ + d];
        __syncthreads();
        #pragma unroll
        for (int al = 0; al < 16; al++) acc += sA[ty][al] * sB[al][tx];
        __syncthreads();
    }
    g_Wbigv[(size_t)c*D_ + d] = acc;
}

// ---------------------------------------------------------------------------
// K_logits: warp-per-group. Stream tokens from GMEM, 8 head accumulators per
// lane, butterfly reduce, in-warp masked softmax, write weights.
// grid = BN/8 blocks x 256 threads.
// ---------------------------------------------------------------------------
__global__ __launch_bounds__(256) void k_logits(const float* __restrict__ s2,
                                                const float* __restrict__ s1,
                                                const int* __restrict__ m2,
                                                const int* __restrict__ m1,
                                                float* __restrict__ maskOut)
{
    __shared__ float sL[8][5][8];   // [warp][row][head]

    int tid = threadIdx.x;
    int wid = tid >> 5, lane = tid & 31;
    int g = blockIdx.x * 8 + wid;

    for (int n = 0; n < 5; n++) {
        const float* src = (n < 3) ? s2 + (size_t)(g*3 + n) * D_
                                   : s1 + (size_t)(g*2 + (n-3)) * D_;
        float acc[8] = {};
        #pragma unroll 6
        for (int i = 0; i < 24; i++) {
            int d = lane + 32*i;
            float t = __ldg(src + d);
            float4 u0 = *(const float4*)(g_uT + d*8);
            float4 u1 = *(const float4*)(g_uT + d*8 + 4);
            acc[0] += t*u0.x; acc[1] += t*u0.y; acc[2] += t*u0.z; acc[3] += t*u0.w;
            acc[4] += t*u1.x; acc[5] += t*u1.y; acc[6] += t*u1.z; acc[7] += t*u1.w;
        }
        #pragma unroll
        for (int off = 16; off; off >>= 1)
            #pragma unroll
            for (int h = 0; h < 8; h++)
                acc[h] += __shfl_xor_sync(0xFFFFFFFF, acc[h], off);
        if (lane == 0) {
            #pragma unroll
            for (int h = 0; h < 8; h++) sL[wid][n][h] = acc[h];
        }
    }
    __syncwarp();

    if (lane < 8) {
        int h = lane;
        int mv[5];
        #pragma unroll
        for (int n = 0; n < 5; n++)
            mv[n] = (n < 3) ? m2[g*3 + n] : m1[g*2 + (n-3)];
        float l[5]; bool valid[5]; bool any = false; float mx = -1e30f;
        #pragma unroll
        for (int n = 0; n < 5; n++) {
            valid[n] = (mv[n] == 1);
            l[n] = sL[wid][n][h] + g_bias[A_ + h];
            if (valid[n]) { any = true; mx = fmaxf(mx, l[n]); }
        }
        float w[5], ssum = 0.f;
        #pragma unroll
        for (int n = 0; n < 5; n++) {
            w[n] = valid[n] ? expf(l[n] - mx) : 0.f;
            ssum += w[n];
        }
        float inv = any ? (1.f/ssum) : 0.f;
        float* wp = g_w + (size_t)g*40 + h*5;
        #pragma unroll
        for (int n = 0; n < 5; n++) wp[n] = w[n]*inv;
        if (h == 0) {
            float he = any ? 1.f : 0.f;
            g_hasenc[g] = he;
            if (maskOut) maskOut[g] = he;
        }
    }
}

// ---------------------------------------------------------------------------
// K_vpool_f: fused pooling + v-projection.
// Block: 32 groups x 256 cols, K=768 in chunks of 16.
// Per chunk: load raw token tiles + Wbigv tile; build 8 per-head pooled
// A-tiles in smem (weights in regs); 4x8 micro-tile FFMA GEMM.
// grid = BN/32, 256 threads.
// ---------------------------------------------------------------------------
#define VG 32
#define KC 16
__global__ __launch_bounds__(256) void k_vpool_f(const float* __restrict__ s2,
                                                 const float* __restrict__ s1)
{
    __shared__ float sT[VG*5*17];        // [g*5+n][k], row stride 17 (conflict-free pooling)
    __shared__ float sPool[8*580];       // h plane stride 580 = 16*36+4; [k*36+g]
    __shared__ float sB[KC*260];         // [k][c], row stride 260

    int tid = threadIdx.x;
    int g0 = blockIdx.x * VG;

    // pooling-build role: fixed (hb, gb)
    int hb = tid >> 5, gb = tid & 31;
    float w0, w1, w2, w3, w4;
    {
        const float* wp = g_w + (size_t)(g0 + gb)*40 + hb*5;
        w0 = wp[0]; w1 = wp[1]; w2 = wp[2]; w3 = wp[3]; w4 = wp[4];
    }

    // GEMM role: tm = warp (4 g-rows), tn = lane (8 cols, single head)
    int tm = tid >> 5;       // 0..7
    int tn = tid & 31;       // 0..31
    int h2 = tn >> 2;        // head of my 8 cols

    float acc[4][8] = {};

    for (int k0 = 0; k0 < D_; k0 += KC) {
        // load token tiles: 160 rows x 4 float4
        for (int idx = tid; idx < VG*5*4; idx += 256) {
            int row = idx >> 2, part = idx & 3;
            int g = row / 5, n = row - g*5;
            int gg = g0 + g;
            const float* src = (n < 3) ? s2 + (size_t)(gg*3 + n) * D_
                                       : s1 + (size_t)(gg*2 + (n-3)) * D_;
            float4 v = *(const float4*)(src + k0 + part*4);
            float* dst = &sT[row*17 + part*4];
            dst[0] = v.x; dst[1] = v.y; dst[2] = v.z; dst[3] = v.w;
        }
        // load B tile: 256 c x 4 float4 -> transposed [k][c]
        for (int idx = tid; idx < 1024; idx += 256) {
            int c = idx >> 2, part = idx & 3;
            float4 v = *(const float4*)(g_Wbigv + (size_t)c*D_ + k0 + part*4);
            sB[(part*4+0)*260 + c] = v.x;
            sB[(part*4+1)*260 + c] = v.y;
            sB[(part*4+2)*260 + c] = v.z;
            sB[(part*4+3)*260 + c] = v.w;
        }
        __syncthreads();

        // build pooled A: sPool[hb][k][gb]
        {
            const float* t0 = &sT[(gb*5+0)*17];
            const float* t1 = &sT[(gb*5+1)*17];
            const float* t2 = &sT[(gb*5+2)*17];
            const float* t3 = &sT[(gb*5+3)*17];
            const float* t4 = &sT[(gb*5+4)*17];
            float* pp = &sPool[hb*580 + gb];
            #pragma unroll
            for (int k = 0; k < KC; k++)
                pp[k*36] = w0*t0[k] + w1*t1[k] + w2*t2[k] + w3*t3[k] + w4*t4[k];
        }
        __syncthreads();

        // GEMM
        #pragma unroll
        for (int k = 0; k < KC; k++) {
            float4 a = *(const float4*)&sPool[h2*580 + k*36 + tm*4];
            float4 b0 = *(const float4*)&sB[k*260 + tn*8];
            float4 b1 = *(const float4*)&sB[k*260 + tn*8 + 4];
            float av[4] = {a.x, a.y, a.z, a.w};
            float bv[8] = {b0.x,b0.y,b0.z,b0.w,b1.x,b1.y,b1.z,b1.w};
            #pragma unroll
            for (int i = 0; i < 4; i++)
                #pragma unroll
                for (int j = 0; j < 8; j++)
                    acc[i][j] += av[i]*bv[j];
        }
        __syncthreads();
    }

    int c = tn*8;
    float4 bo0 = *(const float4*)&g_bias[c];
    float4 bo1 = *(const float4*)&g_bias[c+4];
    float bb[8] = {bo0.x,bo0.y,bo0.z,bo0.w,bo1.x,bo1.y,bo1.z,bo1.w};
    #pragma unroll
    for (int i = 0; i < 4; i++) {
        int g = g0 + tm*4 + i;
        float4 o0, o1;
        o0.x = acc[i][0]+bb[0]; o0.y = acc[i][1]+bb[1];
        o0.z = acc[i][2]+bb[2]; o0.w = acc[i][3]+bb[3];
        o1.x = acc[i][4]+bb[4]; o1.y = acc[i][5]+bb[5];
        o1.z = acc[i][6]+bb[6]; o1.w = acc[i][7]+bb[7];
        *(float4*)&g_pool[(size_t)g*A_ + c]     = o0;
        *(float4*)&g_pool[(size_t)g*A_ + c + 4] = o1;
    }
}

// ---------------------------------------------------------------------------
// K_out: out = pooled_v @ Wout^T + bout, zeroed where no valid key.
// Tile: 64 m x 128 j, K=256, 128 threads, 8x8 micro-tile. grid = (6, 128).
// ---------------------------------------------------------------------------
__global__ __launch_bounds__(128) void k_out(const float* __restrict__ Wout,
                                             const float* __restrict__ bout,
                                             float* __restrict__ out)
{
    __shared__ float sA[16][68];   // [k][m]
    __shared__ float sB[16][132];  // [k][j]
    int tid = threadIdx.x;
    int m0 = blockIdx.y * 64;
    int j0 = blockIdx.x * 128;

    int tm = tid >> 4;
    int tn = tid & 15;

    const float* Ap = g_pool + (size_t)(m0 + (tid >> 1))*A_ + (tid & 1)*8;
    const float* Bp = Wout + (size_t)(j0 + tid)*A_;

    float acc[8][8] = {};

    for (int k0 = 0; k0 < A_; k0 += 16) {
        {
            int row = tid >> 1, kc = (tid & 1)*8;
            float4 v0 = *(const float4*)(Ap + k0);
            float4 v1 = *(const float4*)(Ap + k0 + 4);
            sA[kc+0][row] = v0.x; sA[kc+1][row] = v0.y;
            sA[kc+2][row] = v0.z; sA[kc+3][row] = v0.w;
            sA[kc+4][row] = v1.x; sA[kc+5][row] = v1.y;
            sA[kc+6][row] = v1.z; sA[kc+7][row] = v1.w;
        }
        #pragma unroll
        for (int c = 0; c < 4; c++) {
            float4 v = *(const float4*)(Bp + k0 + c*4);
            sB[c*4+0][tid] = v.x; sB[c*4+1][tid] = v.y;
            sB[c*4+2][tid] = v.z; sB[c*4+3][tid] = v.w;
        }
        __syncthreads();

        #pragma unroll
        for (int k = 0; k < 16; k++) {
            float4 a0 = *(const float4*)&sA[k][tm*8];
            float4 a1 = *(const float4*)&sA[k][tm*8+4];
            float4 b0 = *(const float4*)&sB[k][tn*8];
            float4 b1 = *(const float4*)&sB[k][tn*8+4];
            float av[8] = {a0.x,a0.y,a0.z,a0.w,a1.x,a1.y,a1.z,a1.w};
            float bv[8] = {b0.x,b0.y,b0.z,b0.w,b1.x,b1.y,b1.z,b1.w};
            #pragma unroll
            for (int i = 0; i < 8; i++)
                #pragma unroll
                for (int jj = 0; jj < 8; jj++)
                    acc[i][jj] += av[i]*bv[jj];
        }
        __syncthreads();
    }

    int jb = j0 + tn*8;
    float4 bo0 = *(const float4*)(bout + jb);
    float4 bo1 = *(const float4*)(bout + jb + 4);
    float bb[8] = {bo0.x,bo0.y,bo0.z,bo0.w,bo1.x,bo1.y,bo1.z,bo1.w};
    #pragma unroll
    for (int i = 0; i < 8; i++) {
        int m = m0 + tm*8 + i;
        float he = g_hasenc[m];
        float4 o0, o1;
        o0.x = he*(acc[i][0]+bb[0]); o0.y = he*(acc[i][1]+bb[1]);
        o0.z = he*(acc[i][2]+bb[2]); o0.w = he*(acc[i][3]+bb[3]);
        o1.x = he*(acc[i][4]+bb[4]); o1.y = he*(acc[i][5]+bb[5]);
        o1.z = he*(acc[i][6]+bb[6]); o1.w = he*(acc[i][7]+bb[7]);
        *(float4*)&out[(size_t)m*D_ + jb]     = o0;
        *(float4*)&out[(size_t)m*D_ + jb + 4] = o1;
    }
}

// ---------------------------------------------------------------------------
extern "C" void kernel_launch(void* const* d_in, const int* in_sizes, int n_in,
                              void* d_out, int out_size)
{
    const float* s2   = (const float*)d_in[0];
    const float* s1   = (const float*)d_in[1];
    const float* Win  = (const float*)d_in[2];
    const float* bin  = (const float*)d_in[3];
    const float* Wk   = (const float*)d_in[4];
    const float* bk   = (const float*)d_in[5];
    const float* Wv   = (const float*)d_in[6];
    const float* bv   = (const float*)d_in[7];
    const float* Wout = (const float*)d_in[8];
    const float* bout = (const float*)d_in[9];
    const float* q    = (const float*)d_in[10];
    const int*   m2   = (const int*)d_in[11];
    const int*   m1   = (const int*)d_in[12];

    float* out = (float*)d_out;
    float* maskOut = (out_size >= (int)((size_t)BN*D_ + BN)) ? (out + (size_t)BN*D_)
                                                             : nullptr;

    k_prep<<<1, 256>>>(Wk, bk, Wv, bv, bin, q);
    k_u<<<3, 256>>>(Win);
    k_wbigv<<<dim3(48, 16), dim3(16, 16)>>>(Win, Wv);
    k_logits<<<BN/8, 256>>>(s2, s1, m2, m1, maskOut);
    k_vpool_f<<<BN/VG, 256>>>(s2, s1);
    k_out<<<dim3(6, 128), 128>>>(Wout, bout, out);
}

// round 7
// speedup vs baseline: 1.4078x; 1.1285x over previous
#include <cuda_runtime.h>
#include <math.h>

// Problem constants
#define BN    8192        // B*H*W*T
#define D_    768
#define A_    256
#define HEADS 8
#define HD    32

// Scratch (static device globals; allocation-free)
__device__ float g_U[A_*HEADS];                  // r[a][h]
__device__ float g_bias[A_+HEADS];               // [0..255] bias_v; [256..263] logit const
__device__ float g_uT[D_*HEADS];                 // u transposed: [d][h]
__device__ float g_Wbigv[(size_t)A_*D_];         // Wv @ Win, [c][d]
__device__ float g_w[(size_t)BN*HEADS*5];        // softmax weights [g][h][n]
__device__ float g_pool[(size_t)BN*A_];          // pooled v vectors [g][c]
__device__ float g_hasenc[BN];                   // 1.0 if any valid key else 0.0

// ---------------------------------------------------------------------------
// K_prep: r[a][h], bias_v[c], logit consts c_h.
// ---------------------------------------------------------------------------
__global__ void k_prep(const float* __restrict__ Wk, const float* __restrict__ bk,
                       const float* __restrict__ Wv, const float* __restrict__ bv,
                       const float* __restrict__ bin, const float* __restrict__ q)
{
    int a = threadIdx.x;  // 0..255
    const float scale = rsqrtf((float)HD);

    #pragma unroll
    for (int h = 0; h < HEADS; h++) {
        float u = 0.f;
        #pragma unroll 8
        for (int d = 0; d < HD; d++) {
            int row = h*HD + d;
            u += Wk[row*A_ + a] * (q[row] * scale);
        }
        g_U[a*HEADS + h] = u;
    }

    float bb = bv[a];
    for (int i = 0; i < A_; i++) bb += Wv[a*A_ + i] * bin[i];
    g_bias[a] = bb;

    __syncthreads();

    if (a < HEADS) {
        float c = 0.f;
        for (int i = 0; i < A_; i++) c += g_U[i*HEADS + a] * bin[i];
        for (int d = 0; d < HD; d++) {
            int row = a*HD + d;
            c += q[row] * scale * bk[row];
        }
        g_bias[A_ + a] = c;
    }
}

// ---------------------------------------------------------------------------
// K_u: uT[d][h] = sum_a r[a][h] * Win[a][d].
// ---------------------------------------------------------------------------
__global__ void k_u(const float* __restrict__ Win)
{
    __shared__ float rs[A_*HEADS];
    int tid = threadIdx.x;
    for (int i = tid; i < A_*HEADS; i += 256) rs[i] = g_U[i];
    __syncthreads();

    int d = blockIdx.x*256 + tid;
    float acc[HEADS] = {};
    for (int a = 0; a < A_; a++) {
        float w = Win[(size_t)a*D_ + d];
        #pragma unroll
        for (int h = 0; h < HEADS; h++) acc[h] += w * rs[a*HEADS + h];
    }
    #pragma unroll
    for (int h = 0; h < HEADS; h++) g_uT[d*HEADS + h] = acc[h];
}

// ---------------------------------------------------------------------------
// K_wbigv: W_bigv[c][d] = sum_a Wv[c][a] * Win[a][d].  (256x768, K=256)
// ---------------------------------------------------------------------------
__global__ void k_wbigv(const float* __restrict__ Win, const float* __restrict__ Wv)
{
    __shared__ float sA[16][17];
    __shared__ float sB[16][17];
    int tx = threadIdx.x, ty = threadIdx.y;
    int c = blockIdx.y*16 + ty;
    int d = blockIdx.x*16 + tx;
    float acc = 0.f;

    for (int a0 = 0; a0 < A_; a0 += 16) {
        sA[ty][tx] = Wv[(size_t)c*A_ + a0 + tx];
        sB[ty][tx] = Win[(size_t)(a0+ty)*D_ + d];
        __syncthreads();
        #pragma unroll
        for (int al = 0; al < 16; al++) acc += sA[ty][al] * sB[al][tx];
        __syncthreads();
    }
    g_Wbigv[(size_t)c*D_ + d] = acc;
}

// ---------------------------------------------------------------------------
// K_logits: u in REGISTERS (24 per lane), block handles 16 groups.
// Warp w owns d-slice [w*96, w*96+96); lane owns d0, d0+32, d0+64.
// Token rows read once, fully coalesced. grid = BN/16.
// ---------------------------------------------------------------------------
#define GL 16
__global__ __launch_bounds__(256) void k_logits(const float* __restrict__ s2,
                                                const float* __restrict__ s1,
                                                const int* __restrict__ m2,
                                                const int* __restrict__ m1,
                                                float* __restrict__ maskOut)
{
    __shared__ float sPart[5][8][8];   // [n][warp][h]

    int tid = threadIdx.x;
    int w = tid >> 5, lane = tid & 31;
    int d0 = w*96 + lane;

    // u registers: 3 d-values x 8 heads
    float u0[8], u1[8], u2[8];
    *(float4*)&u0[0] = *(const float4*)(g_uT + (size_t)d0*8);
    *(float4*)&u0[4] = *(const float4*)(g_uT + (size_t)d0*8 + 4);
    *(float4*)&u1[0] = *(const float4*)(g_uT + (size_t)(d0+32)*8);
    *(float4*)&u1[4] = *(const float4*)(g_uT + (size_t)(d0+32)*8 + 4);
    *(float4*)&u2[0] = *(const float4*)(g_uT + (size_t)(d0+64)*8);
    *(float4*)&u2[4] = *(const float4*)(g_uT + (size_t)(d0+64)*8 + 4);

    int gbase = blockIdx.x * GL;

    for (int gi = 0; gi < GL; gi++) {
        int g = gbase + gi;

        #pragma unroll
        for (int n = 0; n < 5; n++) {
            const float* src = (n < 3) ? s2 + (size_t)(g*3 + n) * D_
                                       : s1 + (size_t)(g*2 + (n-3)) * D_;
            float t0 = src[d0], t1 = src[d0+32], t2 = src[d0+64];
            float acc[8];
            #pragma unroll
            for (int h = 0; h < 8; h++)
                acc[h] = t0*u0[h] + t1*u1[h] + t2*u2[h];
            #pragma unroll
            for (int off = 16; off; off >>= 1)
                #pragma unroll
                for (int h = 0; h < 8; h++)
                    acc[h] += __shfl_xor_sync(0xFFFFFFFF, acc[h], off);
            if (lane == 0) {
                #pragma unroll
                for (int h = 0; h < 8; h++) sPart[n][w][h] = acc[h];
            }
        }
        __syncthreads();

        if (tid < 8) {
            int h = tid;
            float l[5];
            #pragma unroll
            for (int n = 0; n < 5; n++) {
                float s = g_bias[A_ + h];
                #pragma unroll
                for (int ww = 0; ww < 8; ww++) s += sPart[n][ww][h];
                l[n] = s;
            }
            bool valid[5]; bool any = false; float mx = -1e30f;
            #pragma unroll
            for (int n = 0; n < 5; n++) {
                int mv = (n < 3) ? m2[g*3 + n] : m1[g*2 + (n-3)];
                valid[n] = (mv == 1);
                if (valid[n]) { any = true; mx = fmaxf(mx, l[n]); }
            }
            float e[5], ssum = 0.f;
            #pragma unroll
            for (int n = 0; n < 5; n++) {
                e[n] = valid[n] ? expf(l[n] - mx) : 0.f;
                ssum += e[n];
            }
            float inv = any ? (1.f/ssum) : 0.f;
            float* wp = g_w + (size_t)g*40 + h*5;
            #pragma unroll
            for (int n = 0; n < 5; n++) wp[n] = e[n]*inv;
            if (h == 0) {
                float he = any ? 1.f : 0.f;
                g_hasenc[g] = he;
                if (maskOut) maskOut[g] = he;
            }
        }
        __syncthreads();
    }
}

// ---------------------------------------------------------------------------
// K_vpool_f: fused pooling + v-projection, KC=16, STATIC smem (35KB).
// Split-role loading: warps 0-3 pool tokens (pool-on-load, float4),
// warps 4-7 load/transpose the Wbigv tile. All warps GEMM.
// grid = BN/32, 256 threads, 2 CTAs/SM.
// ---------------------------------------------------------------------------
#define VG 32
#define KC 16
#define SPG 36                      // sPool g-stride (VG+4 pad)
#define PLANE (KC*SPG + 4)          // 580: head-plane stride (bank rotate)
#define SBS 260                     // sB c-stride

__global__ __launch_bounds__(256, 2) void k_vpool_f(const float* __restrict__ s2,
                                                    const float* __restrict__ s1)
{
    __shared__ float sPool[8*PLANE];    // [h*PLANE + k*SPG + g]
    __shared__ float sB[KC*SBS];        // [k*SBS + c]

    int tid = threadIdx.x;
    int g0 = blockIdx.x * VG;

    bool isPool = tid < 128;
    int gb = tid & 31;                  // pool role: group
    int kp = (tid >> 5) & 3;            // pool role: k-chunk (float4)
    int gg = g0 + gb;

    // per-thread softmax weights + token pointers (pool threads only)
    float wv[40];
    const float* tp[5];
    if (isPool) {
        const float4* wp = (const float4*)(g_w + (size_t)gg*40);
        #pragma unroll
        for (int i = 0; i < 10; i++) *(float4*)&wv[i*4] = wp[i];
        #pragma unroll
        for (int n = 0; n < 5; n++)
            tp[n] = (n < 3) ? s2 + (size_t)(gg*3 + n) * D_
                            : s1 + (size_t)(gg*2 + (n-3)) * D_;
    }
    int bcol = tid - 128;               // B role: base col (0..127), also +128

    // GEMM role: tm = warp (4 g-rows), tn = lane (8 cols), head = tn>>2
    int tm = tid >> 5, tn = tid & 31;
    int h2 = tn >> 2;

    float acc[4][8] = {};

    for (int k0 = 0; k0 < D_; k0 += KC) {
        if (isPool) {
            // pool-on-load: 5 token float4 -> 8 pooled head float4
            float4 t[5];
            #pragma unroll
            for (int n = 0; n < 5; n++)
                t[n] = *(const float4*)(tp[n] + k0 + kp*4);
            #pragma unroll
            for (int h = 0; h < 8; h++) {
                float w0 = wv[h*5+0], w1 = wv[h*5+1], w2 = wv[h*5+2],
                      w3 = wv[h*5+3], w4 = wv[h*5+4];
                float px = w0*t[0].x + w1*t[1].x + w2*t[2].x + w3*t[3].x + w4*t[4].x;
                float py = w0*t[0].y + w1*t[1].y + w2*t[2].y + w3*t[3].y + w4*t[4].y;
                float pz = w0*t[0].z + w1*t[1].z + w2*t[2].z + w3*t[3].z + w4*t[4].z;
                float pw = w0*t[0].w + w1*t[1].w + w2*t[2].w + w3*t[3].w + w4*t[4].w;
                float* dst = &sPool[h*PLANE + (kp*4)*SPG + gb];
                dst[0*SPG] = px; dst[1*SPG] = py; dst[2*SPG] = pz; dst[3*SPG] = pw;
            }
        } else {
            // B tile: 2 cols per thread, 4 float4 each -> transposed [k][c]
            #pragma unroll
            for (int cc = 0; cc < 2; cc++) {
                int c = bcol + cc*128;
                const float* bp = g_Wbigv + (size_t)c*D_ + k0;
                #pragma unroll
                for (int p = 0; p < 4; p++) {
                    float4 v = *(const float4*)(bp + p*4);
                    sB[(p*4+0)*SBS + c] = v.x;
                    sB[(p*4+1)*SBS + c] = v.y;
                    sB[(p*4+2)*SBS + c] = v.z;
                    sB[(p*4+3)*SBS + c] = v.w;
                }
            }
        }
        __syncthreads();

        // GEMM: 4g x 8c micro-tile
        #pragma unroll
        for (int k = 0; k < KC; k++) {
            float4 a  = *(const float4*)&sPool[h2*PLANE + k*SPG + tm*4];
            float4 b0 = *(const float4*)&sB[k*SBS + tn*8];
            float4 b1 = *(const float4*)&sB[k*SBS + tn*8 + 4];
            float av[4] = {a.x, a.y, a.z, a.w};
            float bw[8] = {b0.x,b0.y,b0.z,b0.w,b1.x,b1.y,b1.z,b1.w};
            #pragma unroll
            for (int i = 0; i < 4; i++)
                #pragma unroll
                for (int j = 0; j < 8; j++)
                    acc[i][j] += av[i]*bw[j];
        }
        __syncthreads();
    }

    int c = tn*8;
    float4 bo0 = *(const float4*)&g_bias[c];
    float4 bo1 = *(const float4*)&g_bias[c+4];
    float bb[8] = {bo0.x,bo0.y,bo0.z,bo0.w,bo1.x,bo1.y,bo1.z,bo1.w};
    #pragma unroll
    for (int i = 0; i < 4; i++) {
        int g = g0 + tm*4 + i;
        float4 o0, o1;
        o0.x = acc[i][0]+bb[0]; o0.y = acc[i][1]+bb[1];
        o0.z = acc[i][2]+bb[2]; o0.w = acc[i][3]+bb[3];
        o1.x = acc[i][4]+bb[4]; o1.y = acc[i][5]+bb[5];
        o1.z = acc[i][6]+bb[6]; o1.w = acc[i][7]+bb[7];
        *(float4*)&g_pool[(size_t)g*A_ + c]     = o0;
        *(float4*)&g_pool[(size_t)g*A_ + c + 4] = o1;
    }
}

// ---------------------------------------------------------------------------
// K_out: out = pooled_v @ Wout^T + bout, zeroed where no valid key.
// Tile: 64 m x 128 j, K=256, KC=32, 128 threads, 8x8 micro-tile.
// ---------------------------------------------------------------------------
__global__ __launch_bounds__(128) void k_out(const float* __restrict__ Wout,
                                             const float* __restrict__ bout,
                                             float* __restrict__ out)
{
    __shared__ float sA[32][68];   // [k][m]
    __shared__ float sB[32][132];  // [k][j]
    int tid = threadIdx.x;
    int m0 = blockIdx.y * 64;
    int j0 = blockIdx.x * 128;

    int tm = tid >> 4;
    int tn = tid & 15;

    const float* Ap = g_pool + (size_t)(m0 + (tid >> 1))*A_ + (tid & 1)*16;
    const float* Bp = Wout + (size_t)(j0 + tid)*A_;

    float acc[8][8] = {};

    for (int k0 = 0; k0 < A_; k0 += 32) {
        {
            int row = tid >> 1, kc = (tid & 1)*16;
            #pragma unroll
            for (int p = 0; p < 4; p++) {
                float4 v = *(const float4*)(Ap + k0 + p*4);
                sA[kc+p*4+0][row] = v.x; sA[kc+p*4+1][row] = v.y;
                sA[kc+p*4+2][row] = v.z; sA[kc+p*4+3][row] = v.w;
            }
        }
        #pragma unroll
        for (int p = 0; p < 8; p++) {
            float4 v = *(const float4*)(Bp + k0 + p*4);
            sB[p*4+0][tid] = v.x; sB[p*4+1][tid] = v.y;
            sB[p*4+2][tid] = v.z; sB[p*4+3][tid] = v.w;
        }
        __syncthreads();

        #pragma unroll 16
        for (int k = 0; k < 32; k++) {
            float4 a0 = *(const float4*)&sA[k][tm*8];
            float4 a1 = *(const float4*)&sA[k][tm*8+4];
            float4 b0 = *(const float4*)&sB[k][tn*8];
            float4 b1 = *(const float4*)&sB[k][tn*8+4];
            float av[8] = {a0.x,a0.y,a0.z,a0.w,a1.x,a1.y,a1.z,a1.w};
            float bw[8] = {b0.x,b0.y,b0.z,b0.w,b1.x,b1.y,b1.z,b1.w};
            #pragma unroll
            for (int i = 0; i < 8; i++)
                #pragma unroll
                for (int jj = 0; jj < 8; jj++)
                    acc[i][jj] += av[i]*bw[jj];
        }
        __syncthreads();
    }

    int jb = j0 + tn*8;
    float4 bo0 = *(const float4*)(bout + jb);
    float4 bo1 = *(const float4*)(bout + jb + 4);
    float bb[8] = {bo0.x,bo0.y,bo0.z,bo0.w,bo1.x,bo1.y,bo1.z,bo1.w};
    #pragma unroll
    for (int i = 0; i < 8; i++) {
        int m = m0 + tm*8 + i;
        float he = g_hasenc[m];
        float4 o0, o1;
        o0.x = he*(acc[i][0]+bb[0]); o0.y = he*(acc[i][1]+bb[1]);
        o0.z = he*(acc[i][2]+bb[2]); o0.w = he*(acc[i][3]+bb[3]);
        o1.x = he*(acc[i][4]+bb[4]); o1.y = he*(acc[i][5]+bb[5]);
        o1.z = he*(acc[i][6]+bb[6]); o1.w = he*(acc[i][7]+bb[7]);
        *(float4*)&out[(size_t)m*D_ + jb]     = o0;
        *(float4*)&out[(size_t)m*D_ + jb + 4] = o1;
    }
}

// ---------------------------------------------------------------------------
extern "C" void kernel_launch(void* const* d_in, const int* in_sizes, int n_in,
                              void* d_out, int out_size)
{
    const float* s2   = (const float*)d_in[0];
    const float* s1   = (const float*)d_in[1];
    const float* Win  = (const float*)d_in[2];
    const float* bin  = (const float*)d_in[3];
    const float* Wk   = (const float*)d_in[4];
    const float* bk   = (const float*)d_in[5];
    const float* Wv   = (const float*)d_in[6];
    const float* bv   = (const float*)d_in[7];
    const float* Wout = (const float*)d_in[8];
    const float* bout = (const float*)d_in[9];
    const float* q    = (const float*)d_in[10];
    const int*   m2   = (const int*)d_in[11];
    const int*   m1   = (const int*)d_in[12];

    float* out = (float*)d_out;
    float* maskOut = (out_size >= (int)((size_t)BN*D_ + BN)) ? (out + (size_t)BN*D_)
                                                             : nullptr;

    k_prep<<<1, 256>>>(Wk, bk, Wv, bv, bin, q);
    k_u<<<3, 256>>>(Win);
    k_wbigv<<<dim3(48, 16), dim3(16, 16)>>>(Win, Wv);
    k_logits<<<BN/GL, 256>>>(s2, s1, m2, m1, maskOut);
    k_vpool_f<<<BN/VG, 256>>>(s2, s1);
    k_out<<<dim3(6, 128), 128>>>(Wout, bout, out);
}